// round 6
// baseline (speedup 1.0000x reference)
#include <cuda_runtime.h>

#define YD 384
#define XD 512
#define EPSR 1e-4f

__global__ __launch_bounds__(128) void quadfit_kernel(
    const float* __restrict__ feat0,
    const float* __restrict__ feat1,
    const float* __restrict__ flow,
    float* __restrict__ out)
{
    __shared__ float c_s[128 * 9];
    const int w    = threadIdx.x >> 5;   // warp 0..3
    const int lane = threadIdx.x & 31;
    const int g    = lane >> 3;          // pixel group within warp 0..3
    const int s    = lane & 7;           // sublane = float4 channel slot 0..7
    const int base = blockIdx.x * 128;

    const float4* __restrict__ f0v = (const float4*)feat0;
    const float4* __restrict__ f1v = (const float4*)feat1;

    // ---------------- Phase A: warp covers pixels [w*32, w*32+32), 4 px per iteration ----------------
#pragma unroll 1
    for (int it = 0; it < 8; ++it) {
        const int li  = w * 32 + it * 4 + g;  // local pixel in block
        const int p   = base + li;            // linear pixel
        const int pyi = p >> 9;               // X = 512
        const int pxi = p & 511;

        const float u = __ldg(flow + p * 3 + 0);
        const float v = __ldg(flow + p * 3 + 1);
        const float px = (float)pxi + u;
        const float py = (float)pyi + v;
        const float bxf = floorf(px), byf = floorf(py);
        const float wx = px - bxf, wy = py - byf;
        const int bx = (int)bxf, by = (int)byf;

        const float4 f0 = f0v[p * 8 + s];

        const bool interior = (bx >= 1) && (bx <= XD - 3) && (by >= 1) && (by <= YD - 3);
        if (interior) {
            const float4* rp = f1v + ((size_t)(by - 1) * XD + (bx - 1)) * 8 + s;
            float4 hp0, hp1, hp2;   // previous row horizontal lerps
            {
                float4 p0 = __ldg(rp + 0);
                float4 p1 = __ldg(rp + 8);
                float4 p2 = __ldg(rp + 16);
                float4 p3 = __ldg(rp + 24);
                hp0.x = p0.x + wx * (p1.x - p0.x); hp0.y = p0.y + wx * (p1.y - p0.y);
                hp0.z = p0.z + wx * (p1.z - p0.z); hp0.w = p0.w + wx * (p1.w - p0.w);
                hp1.x = p1.x + wx * (p2.x - p1.x); hp1.y = p1.y + wx * (p2.y - p1.y);
                hp1.z = p1.z + wx * (p2.z - p1.z); hp1.w = p1.w + wx * (p2.w - p1.w);
                hp2.x = p2.x + wx * (p3.x - p2.x); hp2.y = p2.y + wx * (p3.y - p2.y);
                hp2.z = p2.z + wx * (p3.z - p2.z); hp2.w = p2.w + wx * (p3.w - p2.w);
            }
#pragma unroll
            for (int r = 1; r < 4; r++) {
                const float4* q = rp + r * (XD * 8);
                float4 p0 = __ldg(q + 0);
                float4 p1 = __ldg(q + 8);
                float4 p2 = __ldg(q + 16);
                float4 p3 = __ldg(q + 24);
                float4 hc0, hc1, hc2;
                hc0.x = p0.x + wx * (p1.x - p0.x); hc0.y = p0.y + wx * (p1.y - p0.y);
                hc0.z = p0.z + wx * (p1.z - p0.z); hc0.w = p0.w + wx * (p1.w - p0.w);
                hc1.x = p1.x + wx * (p2.x - p1.x); hc1.y = p1.y + wx * (p2.y - p1.y);
                hc1.z = p1.z + wx * (p2.z - p1.z); hc1.w = p1.w + wx * (p2.w - p1.w);
                hc2.x = p2.x + wx * (p3.x - p2.x); hc2.y = p2.y + wx * (p3.y - p2.y);
                hc2.z = p2.z + wx * (p3.z - p2.z); hc2.w = p2.w + wx * (p3.w - p2.w);
                // 3 cost samples for this row pair; reduce + store immediately
#pragma unroll
                for (int cc = 0; cc < 3; cc++) {
                    const float4 hp = (cc == 0) ? hp0 : (cc == 1) ? hp1 : hp2;
                    const float4 hc = (cc == 0) ? hc0 : (cc == 1) ? hc1 : hc2;
                    float vx = hp.x + wy * (hc.x - hp.x);
                    float vy = hp.y + wy * (hc.y - hp.y);
                    float vz = hp.z + wy * (hc.z - hp.z);
                    float vw = hp.w + wy * (hc.w - hp.w);
                    float dx = f0.x - vx, dy = f0.y - vy, dz = f0.z - vz, dw = f0.w - vw;
                    float vr = dx * dx + dy * dy + dz * dz + dw * dw;
                    vr += __shfl_xor_sync(0xffffffffu, vr, 4);
                    vr += __shfl_xor_sync(0xffffffffu, vr, 2);
                    vr += __shfl_xor_sync(0xffffffffu, vr, 1);
                    if (s == 0) c_s[li * 9 + (r - 1) * 3 + cc] = vr;
                }
                hp0 = hc0; hp1 = hc1; hp2 = hc2;
            }
        } else {
            // exact clamped path (matches reference: x1 = clip(clip(x0)+1))
#pragma unroll 1
            for (int k = 0; k < 9; k++) {
                const int ox = k % 3 - 1, oy = k / 3 - 1;
                int x0 = min(max(bx + ox, 0), XD - 1);
                int x1 = min(x0 + 1, XD - 1);
                int y0 = min(max(by + oy, 0), YD - 1);
                int y1 = min(y0 + 1, YD - 1);
                float4 f00 = __ldg(f1v + ((size_t)y0 * XD + x0) * 8 + s);
                float4 f01 = __ldg(f1v + ((size_t)y0 * XD + x1) * 8 + s);
                float4 f10 = __ldg(f1v + ((size_t)y1 * XD + x0) * 8 + s);
                float4 f11 = __ldg(f1v + ((size_t)y1 * XD + x1) * 8 + s);
                float tx = f00.x + wx * (f01.x - f00.x);
                float ty = f00.y + wx * (f01.y - f00.y);
                float tz = f00.z + wx * (f01.z - f00.z);
                float tw = f00.w + wx * (f01.w - f00.w);
                float bxv = f10.x + wx * (f11.x - f10.x);
                float byv = f10.y + wx * (f11.y - f10.y);
                float bzv = f10.z + wx * (f11.z - f10.z);
                float bwv = f10.w + wx * (f11.w - f10.w);
                float vx = tx + wy * (bxv - tx);
                float vy = ty + wy * (byv - ty);
                float vz = tz + wy * (bzv - tz);
                float vw = tw + wy * (bwv - tw);
                float dx = f0.x - vx, dy = f0.y - vy, dz = f0.z - vz, dw = f0.w - vw;
                float vr = dx * dx + dy * dy + dz * dz + dw * dw;
                vr += __shfl_xor_sync(0xffffffffu, vr, 4);
                vr += __shfl_xor_sync(0xffffffffu, vr, 2);
                vr += __shfl_xor_sync(0xffffffffu, vr, 1);
                if (s == 0) c_s[li * 9 + k] = vr;
            }
        }
    }

    __syncwarp();

    // ---------------- Phase B: warp-local, lane-per-pixel softmax + 6x6 solve ----------------
    {
        const int t = w * 32 + lane;    // this warp's own 32 pixels — no cross-warp smem reads
        const int p = base + t;

        float c[9];
#pragma unroll
        for (int k = 0; k < 9; k++) c[k] = c_s[t * 9 + k];

        // softmax(-c), normalized weights
        float m = c[0];
#pragma unroll
        for (int k = 1; k < 9; k++) m = fminf(m, c[k]);
        float wgt[9];
        float sums = 0.f;
#pragma unroll
        for (int k = 0; k < 9; k++) { wgt[k] = __expf(m - c[k]); sums += wgt[k]; }
        const float inv_s = 1.f / sums;
#pragma unroll
        for (int k = 0; k < 9; k++) wgt[k] *= inv_s;

        // AtWA (lower triangle, idx(i,j)=i*(i+1)/2+j) and rhs
        float M[21];
        float r6[6];
#pragma unroll
        for (int i = 0; i < 21; i++) M[i] = 0.f;
#pragma unroll
        for (int i = 0; i < 6; i++) r6[i] = 0.f;
#pragma unroll
        for (int k = 0; k < 9; k++) {
            const float ox = (float)(k % 3 - 1);
            const float oy = (float)(k / 3 - 1);
            const float a[6] = {ox * ox, oy * oy, ox * oy, ox, oy, 1.f};
            const float wk = wgt[k];
            const float wc = wk * c[k];
            int idx = 0;
#pragma unroll
            for (int i = 0; i < 6; i++) {
                r6[i] += a[i] * wc;
#pragma unroll
                for (int j = 0; j <= i; j++) { M[idx] += a[i] * a[j] * wk; idx++; }
            }
        }
        M[0] += EPSR; M[2] += EPSR; M[5] += EPSR; M[9] += EPSR; M[14] += EPSR; M[20] += EPSR;

        // in-place Cholesky: M becomes L (bit-identical to separate-Lm version)
        float invd[6];
#pragma unroll
        for (int j = 0; j < 6; j++) {
            float d = M[j * (j + 1) / 2 + j];
#pragma unroll
            for (int k2 = 0; k2 < j; k2++) { float l = M[j * (j + 1) / 2 + k2]; d -= l * l; }
            const float iv = rsqrtf(d);
            invd[j] = iv;
            M[j * (j + 1) / 2 + j] = d * iv;
#pragma unroll
            for (int i = j + 1; i < 6; i++) {
                float sij = M[i * (i + 1) / 2 + j];
#pragma unroll
                for (int k2 = 0; k2 < j; k2++)
                    sij -= M[i * (i + 1) / 2 + k2] * M[j * (j + 1) / 2 + k2];
                M[i * (i + 1) / 2 + j] = sij * iv;
            }
        }

        // L y = rhs ; L^T x = y
        float xv[6];
        {
            float yv[6];
#pragma unroll
            for (int i = 0; i < 6; i++) {
                float s2 = r6[i];
#pragma unroll
                for (int k2 = 0; k2 < i; k2++) s2 -= M[i * (i + 1) / 2 + k2] * yv[k2];
                yv[i] = s2 * invd[i];
            }
#pragma unroll
            for (int i = 5; i >= 0; i--) {
                float s2 = yv[i];
#pragma unroll
                for (int k2 = i + 1; k2 < 6; k2++) s2 -= M[k2 * (k2 + 1) / 2 + i] * xv[k2];
                xv[i] = s2 * invd[i];
            }
        }

        float2* op = reinterpret_cast<float2*>(out + (size_t)p * 6);
        op[0] = make_float2(xv[0], xv[1]);
        op[1] = make_float2(xv[2], xv[3]);
        op[2] = make_float2(xv[4], xv[5]);
    }
}

extern "C" void kernel_launch(void* const* d_in, const int* in_sizes, int n_in,
                              void* d_out, int out_size)
{
    const float* feat0 = (const float*)d_in[0];
    const float* feat1 = (const float*)d_in[1];
    const float* flow  = (const float*)d_in[2];
    float* out = (float*)d_out;
    quadfit_kernel<<<(YD * XD) / 128, 128>>>(feat0, feat1, flow, out);
}

// round 7
// speedup vs baseline: 1.2402x; 1.2402x over previous
#include <cuda_runtime.h>

#define YD 384
#define XD 512
#define EPSR 1e-4f

__global__ __launch_bounds__(256) void quadfit_kernel(
    const float* __restrict__ feat0,
    const float* __restrict__ feat1,
    const float* __restrict__ flow,
    float* __restrict__ out)
{
    __shared__ float c_s[256 * 9];
    const int w    = threadIdx.x >> 5;   // warp 0..7
    const int lane = threadIdx.x & 31;
    const int g    = lane >> 3;          // pixel group within warp 0..3
    const int s    = lane & 7;           // sublane = float4 channel slot 0..7
    const int base = blockIdx.x * 256;

    const float4* __restrict__ f0v = (const float4*)feat0;
    const float4* __restrict__ f1v = (const float4*)feat1;

    // ---------------- Phase A: 4 pixels per warp, 8 lanes (float4) per pixel ----------------
    // software pipeline: prefetch next iteration's flow + feat0 during current compute
    int p_pre = base + 0 * 32 + w * 4 + g;
    float u_n = __ldg(flow + p_pre * 3 + 0);
    float v_n = __ldg(flow + p_pre * 3 + 1);
    float4 f0_n = f0v[p_pre * 8 + s];

#pragma unroll 1
    for (int it = 0; it < 8; ++it) {
        const int li  = it * 32 + w * 4 + g;  // local pixel in block
        const int p   = base + li;            // linear pixel
        const int pyi = p >> 9;               // X = 512
        const int pxi = p & 511;

        const float u  = u_n;
        const float v  = v_n;
        const float4 f0 = f0_n;

        // issue next iteration's loads NOW (branchless: clamp to last iter)
        {
            const int itn = (it < 7) ? it + 1 : 7;
            const int pn  = base + itn * 32 + w * 4 + g;
            u_n  = __ldg(flow + pn * 3 + 0);
            v_n  = __ldg(flow + pn * 3 + 1);
            f0_n = f0v[pn * 8 + s];
        }

        const float px = (float)pxi + u;
        const float py = (float)pyi + v;
        const float bxf = floorf(px), byf = floorf(py);
        const float wx = px - bxf, wy = py - byf;
        const int bx = (int)bxf, by = (int)byf;

        float c[9];
        const bool interior = (bx >= 1) && (bx <= XD - 3) && (by >= 1) && (by <= YD - 3);
        if (interior) {
            const float4* rp = f1v + ((size_t)(by - 1) * XD + (bx - 1)) * 8 + s;
            float4 hp0, hp1, hp2;   // previous row horizontal lerps
            {
                float4 p0 = __ldg(rp + 0);
                float4 p1 = __ldg(rp + 8);
                float4 p2 = __ldg(rp + 16);
                float4 p3 = __ldg(rp + 24);
                hp0.x = p0.x + wx * (p1.x - p0.x); hp0.y = p0.y + wx * (p1.y - p0.y);
                hp0.z = p0.z + wx * (p1.z - p0.z); hp0.w = p0.w + wx * (p1.w - p0.w);
                hp1.x = p1.x + wx * (p2.x - p1.x); hp1.y = p1.y + wx * (p2.y - p1.y);
                hp1.z = p1.z + wx * (p2.z - p1.z); hp1.w = p1.w + wx * (p2.w - p1.w);
                hp2.x = p2.x + wx * (p3.x - p2.x); hp2.y = p2.y + wx * (p3.y - p2.y);
                hp2.z = p2.z + wx * (p3.z - p2.z); hp2.w = p2.w + wx * (p3.w - p2.w);
            }
#pragma unroll
            for (int r = 1; r < 4; r++) {
                const float4* q = rp + r * (XD * 8);
                float4 p0 = __ldg(q + 0);
                float4 p1 = __ldg(q + 8);
                float4 p2 = __ldg(q + 16);
                float4 p3 = __ldg(q + 24);
                float4 hc0, hc1, hc2;
                hc0.x = p0.x + wx * (p1.x - p0.x); hc0.y = p0.y + wx * (p1.y - p0.y);
                hc0.z = p0.z + wx * (p1.z - p0.z); hc0.w = p0.w + wx * (p1.w - p0.w);
                hc1.x = p1.x + wx * (p2.x - p1.x); hc1.y = p1.y + wx * (p2.y - p1.y);
                hc1.z = p1.z + wx * (p2.z - p1.z); hc1.w = p1.w + wx * (p2.w - p1.w);
                hc2.x = p2.x + wx * (p3.x - p2.x); hc2.y = p2.y + wx * (p3.y - p2.y);
                hc2.z = p2.z + wx * (p3.z - p2.z); hc2.w = p2.w + wx * (p3.w - p2.w);
#pragma unroll
                for (int cc = 0; cc < 3; cc++) {
                    const float4 hp = (cc == 0) ? hp0 : (cc == 1) ? hp1 : hp2;
                    const float4 hc = (cc == 0) ? hc0 : (cc == 1) ? hc1 : hc2;
                    float vx = hp.x + wy * (hc.x - hp.x);
                    float vy = hp.y + wy * (hc.y - hp.y);
                    float vz = hp.z + wy * (hc.z - hp.z);
                    float vw = hp.w + wy * (hc.w - hp.w);
                    float dx = f0.x - vx, dy = f0.y - vy, dz = f0.z - vz, dw = f0.w - vw;
                    c[(r - 1) * 3 + cc] = dx * dx + dy * dy + dz * dz + dw * dw;
                }
                hp0 = hc0; hp1 = hc1; hp2 = hc2;
            }
        } else {
            // exact clamped path (matches reference: x1 = clip(clip(x0)+1))
#pragma unroll 1
            for (int k = 0; k < 9; k++) {
                const int ox = k % 3 - 1, oy = k / 3 - 1;
                int x0 = min(max(bx + ox, 0), XD - 1);
                int x1 = min(x0 + 1, XD - 1);
                int y0 = min(max(by + oy, 0), YD - 1);
                int y1 = min(y0 + 1, YD - 1);
                float4 f00 = __ldg(f1v + ((size_t)y0 * XD + x0) * 8 + s);
                float4 f01 = __ldg(f1v + ((size_t)y0 * XD + x1) * 8 + s);
                float4 f10 = __ldg(f1v + ((size_t)y1 * XD + x0) * 8 + s);
                float4 f11 = __ldg(f1v + ((size_t)y1 * XD + x1) * 8 + s);
                float tx = f00.x + wx * (f01.x - f00.x);
                float ty = f00.y + wx * (f01.y - f00.y);
                float tz = f00.z + wx * (f01.z - f00.z);
                float tw = f00.w + wx * (f01.w - f00.w);
                float bxv = f10.x + wx * (f11.x - f10.x);
                float byv = f10.y + wx * (f11.y - f10.y);
                float bzv = f10.z + wx * (f11.z - f10.z);
                float bwv = f10.w + wx * (f11.w - f10.w);
                float vx = tx + wy * (bxv - tx);
                float vy = ty + wy * (byv - ty);
                float vz = tz + wy * (bzv - tz);
                float vw = tw + wy * (bwv - tw);
                float dx = f0.x - vx, dy = f0.y - vy, dz = f0.z - vz, dw = f0.w - vw;
                c[k] = dx * dx + dy * dy + dz * dz + dw * dw;
            }
        }

        // batch butterfly reduce (9 independent 3-deep chains — full ILP)
#pragma unroll
        for (int k = 0; k < 9; k++) {
            float vr = c[k];
            vr += __shfl_xor_sync(0xffffffffu, vr, 4);
            vr += __shfl_xor_sync(0xffffffffu, vr, 2);
            vr += __shfl_xor_sync(0xffffffffu, vr, 1);
            c[k] = vr;
        }
        if (s == 0) {
#pragma unroll
            for (int k = 0; k < 9; k++) c_s[li * 9 + k] = c[k];
        }
    }

    __syncthreads();

    // ---------------- Phase B: thread-per-pixel softmax + 6x6 solve ----------------
    {
        const int t = threadIdx.x;
        const int p = base + t;

        float c[9];
#pragma unroll
        for (int k = 0; k < 9; k++) c[k] = c_s[t * 9 + k];

        // softmax(-c), normalized weights
        float m = c[0];
#pragma unroll
        for (int k = 1; k < 9; k++) m = fminf(m, c[k]);
        float wgt[9];
        float sums = 0.f;
#pragma unroll
        for (int k = 0; k < 9; k++) { wgt[k] = __expf(m - c[k]); sums += wgt[k]; }
        const float inv_s = 1.f / sums;
#pragma unroll
        for (int k = 0; k < 9; k++) wgt[k] *= inv_s;

        // AtWA (lower triangle, idx(i,j)=i*(i+1)/2+j) and rhs
        float M[21];
        float r6[6];
#pragma unroll
        for (int i = 0; i < 21; i++) M[i] = 0.f;
#pragma unroll
        for (int i = 0; i < 6; i++) r6[i] = 0.f;
#pragma unroll
        for (int k = 0; k < 9; k++) {
            const float ox = (float)(k % 3 - 1);
            const float oy = (float)(k / 3 - 1);
            const float a[6] = {ox * ox, oy * oy, ox * oy, ox, oy, 1.f};
            const float wk = wgt[k];
            const float wc = wk * c[k];
            int idx = 0;
#pragma unroll
            for (int i = 0; i < 6; i++) {
                r6[i] += a[i] * wc;
#pragma unroll
                for (int j = 0; j <= i; j++) { M[idx] += a[i] * a[j] * wk; idx++; }
            }
        }
        M[0] += EPSR; M[2] += EPSR; M[5] += EPSR; M[9] += EPSR; M[14] += EPSR; M[20] += EPSR;

        // in-place Cholesky: M becomes L (bit-identical to separate-Lm version)
        float invd[6];
#pragma unroll
        for (int j = 0; j < 6; j++) {
            float d = M[j * (j + 1) / 2 + j];
#pragma unroll
            for (int k2 = 0; k2 < j; k2++) { float l = M[j * (j + 1) / 2 + k2]; d -= l * l; }
            const float iv = rsqrtf(d);
            invd[j] = iv;
            M[j * (j + 1) / 2 + j] = d * iv;
#pragma unroll
            for (int i = j + 1; i < 6; i++) {
                float sij = M[i * (i + 1) / 2 + j];
#pragma unroll
                for (int k2 = 0; k2 < j; k2++)
                    sij -= M[i * (i + 1) / 2 + k2] * M[j * (j + 1) / 2 + k2];
                M[i * (i + 1) / 2 + j] = sij * iv;
            }
        }

        // L y = rhs ; L^T x = y
        float xv[6];
        {
            float yv[6];
#pragma unroll
            for (int i = 0; i < 6; i++) {
                float s2 = r6[i];
#pragma unroll
                for (int k2 = 0; k2 < i; k2++) s2 -= M[i * (i + 1) / 2 + k2] * yv[k2];
                yv[i] = s2 * invd[i];
            }
#pragma unroll
            for (int i = 5; i >= 0; i--) {
                float s2 = yv[i];
#pragma unroll
                for (int k2 = i + 1; k2 < 6; k2++) s2 -= M[k2 * (k2 + 1) / 2 + i] * xv[k2];
                xv[i] = s2 * invd[i];
            }
        }

        float2* op = reinterpret_cast<float2*>(out + (size_t)p * 6);
        op[0] = make_float2(xv[0], xv[1]);
        op[1] = make_float2(xv[2], xv[3]);
        op[2] = make_float2(xv[4], xv[5]);
    }
}

extern "C" void kernel_launch(void* const* d_in, const int* in_sizes, int n_in,
                              void* d_out, int out_size)
{
    const float* feat0 = (const float*)d_in[0];
    const float* feat1 = (const float*)d_in[1];
    const float* flow  = (const float*)d_in[2];
    float* out = (float*)d_out;
    quadfit_kernel<<<(YD * XD) / 256, 256>>>(feat0, feat1, flow, out);
}

// round 8
// speedup vs baseline: 1.4395x; 1.1607x over previous
#include <cuda_runtime.h>

#define YD 384
#define XD 512
#define EPSR 1e-4f

__global__ __launch_bounds__(256) void quadfit_kernel(
    const float* __restrict__ feat0,
    const float* __restrict__ feat1,
    const float* __restrict__ flow,
    float* __restrict__ out)
{
    __shared__ float c_s[256 * 9];
    __shared__ float uv_s[256 * 2];
    const int w    = threadIdx.x >> 5;   // warp 0..7
    const int lane = threadIdx.x & 31;
    const int g    = lane >> 3;          // pixel group within warp 0..3
    const int s    = lane & 7;           // sublane = float4 channel slot 0..7
    const int base = blockIdx.x * 256;

    const float4* __restrict__ f0v = (const float4*)feat0;
    const float4* __restrict__ f1v = (const float4*)feat1;

    // ---- stage flow (u,v) for the block's 256 pixels: 3 coalesced LDGs/thread
    for (int i = threadIdx.x; i < 768; i += 256) {
        const float val = __ldg(flow + (size_t)base * 3 + i);
        const int px = i / 3, ch = i - px * 3;
        if (ch < 2) uv_s[px * 2 + ch] = val;
    }
    __syncthreads();

    // ---------------- Phase A: 4 pixels per warp, 8 lanes (float4) per pixel ----------------
#pragma unroll 1
    for (int it = 0; it < 8; ++it) {
        const int li  = it * 32 + w * 4 + g;  // local pixel in block
        const int p   = base + li;            // linear pixel
        const int pyi = p >> 9;               // X = 512
        const int pxi = p & 511;

        const float u = uv_s[li * 2 + 0];
        const float v = uv_s[li * 2 + 1];
        const float px = (float)pxi + u;
        const float py = (float)pyi + v;
        const float bxf = floorf(px), byf = floorf(py);
        const float wx = px - bxf, wy = py - byf;
        const int bx = (int)bxf, by = (int)byf;

        const float4 f0 = f0v[p * 8 + s];

        float c[9];
        const bool interior = (bx >= 1) && (bx <= XD - 3) && (by >= 1) && (by <= YD - 3);
        if (interior) {
            const float4* rp = f1v + ((size_t)(by - 1) * XD + (bx - 1)) * 8 + s;
            float4 hp0, hp1, hp2;   // previous row horizontal lerps
            {
                float4 p0 = __ldg(rp + 0);
                float4 p1 = __ldg(rp + 8);
                float4 p2 = __ldg(rp + 16);
                float4 p3 = __ldg(rp + 24);
                hp0.x = p0.x + wx * (p1.x - p0.x); hp0.y = p0.y + wx * (p1.y - p0.y);
                hp0.z = p0.z + wx * (p1.z - p0.z); hp0.w = p0.w + wx * (p1.w - p0.w);
                hp1.x = p1.x + wx * (p2.x - p1.x); hp1.y = p1.y + wx * (p2.y - p1.y);
                hp1.z = p1.z + wx * (p2.z - p1.z); hp1.w = p1.w + wx * (p2.w - p1.w);
                hp2.x = p2.x + wx * (p3.x - p2.x); hp2.y = p2.y + wx * (p3.y - p2.y);
                hp2.z = p2.z + wx * (p3.z - p2.z); hp2.w = p2.w + wx * (p3.w - p2.w);
            }
#pragma unroll
            for (int r = 1; r < 4; r++) {
                const float4* q = rp + r * (XD * 8);
                float4 p0 = __ldg(q + 0);
                float4 p1 = __ldg(q + 8);
                float4 p2 = __ldg(q + 16);
                float4 p3 = __ldg(q + 24);
                float4 hc0, hc1, hc2;
                hc0.x = p0.x + wx * (p1.x - p0.x); hc0.y = p0.y + wx * (p1.y - p0.y);
                hc0.z = p0.z + wx * (p1.z - p0.z); hc0.w = p0.w + wx * (p1.w - p0.w);
                hc1.x = p1.x + wx * (p2.x - p1.x); hc1.y = p1.y + wx * (p2.y - p1.y);
                hc1.z = p1.z + wx * (p2.z - p1.z); hc1.w = p1.w + wx * (p2.w - p1.w);
                hc2.x = p2.x + wx * (p3.x - p2.x); hc2.y = p2.y + wx * (p3.y - p2.y);
                hc2.z = p2.z + wx * (p3.z - p2.z); hc2.w = p2.w + wx * (p3.w - p2.w);
#pragma unroll
                for (int cc = 0; cc < 3; cc++) {
                    const float4 hp = (cc == 0) ? hp0 : (cc == 1) ? hp1 : hp2;
                    const float4 hc = (cc == 0) ? hc0 : (cc == 1) ? hc1 : hc2;
                    float vx = hp.x + wy * (hc.x - hp.x);
                    float vy = hp.y + wy * (hc.y - hp.y);
                    float vz = hp.z + wy * (hc.z - hp.z);
                    float vw = hp.w + wy * (hc.w - hp.w);
                    float dx = f0.x - vx, dy = f0.y - vy, dz = f0.z - vz, dw = f0.w - vw;
                    c[(r - 1) * 3 + cc] = dx * dx + dy * dy + dz * dz + dw * dw;
                }
                hp0 = hc0; hp1 = hc1; hp2 = hc2;
            }
        } else {
            // exact clamped path (matches reference: x1 = clip(clip(x0)+1))
#pragma unroll 1
            for (int k = 0; k < 9; k++) {
                const int ox = k % 3 - 1, oy = k / 3 - 1;
                int x0 = min(max(bx + ox, 0), XD - 1);
                int x1 = min(x0 + 1, XD - 1);
                int y0 = min(max(by + oy, 0), YD - 1);
                int y1 = min(y0 + 1, YD - 1);
                float4 f00 = __ldg(f1v + ((size_t)y0 * XD + x0) * 8 + s);
                float4 f01 = __ldg(f1v + ((size_t)y0 * XD + x1) * 8 + s);
                float4 f10 = __ldg(f1v + ((size_t)y1 * XD + x0) * 8 + s);
                float4 f11 = __ldg(f1v + ((size_t)y1 * XD + x1) * 8 + s);
                float tx = f00.x + wx * (f01.x - f00.x);
                float ty = f00.y + wx * (f01.y - f00.y);
                float tz = f00.z + wx * (f01.z - f00.z);
                float tw = f00.w + wx * (f01.w - f00.w);
                float bxv = f10.x + wx * (f11.x - f10.x);
                float byv = f10.y + wx * (f11.y - f10.y);
                float bzv = f10.z + wx * (f11.z - f10.z);
                float bwv = f10.w + wx * (f11.w - f10.w);
                float vx = tx + wy * (bxv - tx);
                float vy = ty + wy * (byv - ty);
                float vz = tz + wy * (bzv - tz);
                float vw = tw + wy * (bwv - tw);
                float dx = f0.x - vx, dy = f0.y - vy, dz = f0.z - vz, dw = f0.w - vw;
                c[k] = dx * dx + dy * dy + dz * dz + dw * dw;
            }
        }

        // batch butterfly reduce (9 independent 3-deep chains — full ILP)
#pragma unroll
        for (int k = 0; k < 9; k++) {
            float vr = c[k];
            vr += __shfl_xor_sync(0xffffffffu, vr, 4);
            vr += __shfl_xor_sync(0xffffffffu, vr, 2);
            vr += __shfl_xor_sync(0xffffffffu, vr, 1);
            c[k] = vr;
        }
        if (s == 0) {
#pragma unroll
            for (int k = 0; k < 9; k++) c_s[li * 9 + k] = c[k];
        }
    }

    __syncthreads();

    // ---------------- Phase B: thread-per-pixel softmax + 6x6 solve ----------------
    {
        const int t = threadIdx.x;
        const int p = base + t;

        float c[9];
#pragma unroll
        for (int k = 0; k < 9; k++) c[k] = c_s[t * 9 + k];

        // softmax(-c), normalized weights
        float m = c[0];
#pragma unroll
        for (int k = 1; k < 9; k++) m = fminf(m, c[k]);
        float wgt[9];
        float sums = 0.f;
#pragma unroll
        for (int k = 0; k < 9; k++) { wgt[k] = __expf(m - c[k]); sums += wgt[k]; }
        const float inv_s = 1.f / sums;
#pragma unroll
        for (int k = 0; k < 9; k++) wgt[k] *= inv_s;

        // AtWA (lower triangle, idx(i,j)=i*(i+1)/2+j) and rhs
        float M[21];
        float r6[6];
#pragma unroll
        for (int i = 0; i < 21; i++) M[i] = 0.f;
#pragma unroll
        for (int i = 0; i < 6; i++) r6[i] = 0.f;
#pragma unroll
        for (int k = 0; k < 9; k++) {
            const float ox = (float)(k % 3 - 1);
            const float oy = (float)(k / 3 - 1);
            const float a[6] = {ox * ox, oy * oy, ox * oy, ox, oy, 1.f};
            const float wk = wgt[k];
            const float wc = wk * c[k];
            int idx = 0;
#pragma unroll
            for (int i = 0; i < 6; i++) {
                r6[i] += a[i] * wc;
#pragma unroll
                for (int j = 0; j <= i; j++) { M[idx] += a[i] * a[j] * wk; idx++; }
            }
        }
        M[0] += EPSR; M[2] += EPSR; M[5] += EPSR; M[9] += EPSR; M[14] += EPSR; M[20] += EPSR;

        // in-place Cholesky: M becomes L
        float invd[6];
#pragma unroll
        for (int j = 0; j < 6; j++) {
            float d = M[j * (j + 1) / 2 + j];
#pragma unroll
            for (int k2 = 0; k2 < j; k2++) { float l = M[j * (j + 1) / 2 + k2]; d -= l * l; }
            const float iv = rsqrtf(d);
            invd[j] = iv;
            M[j * (j + 1) / 2 + j] = d * iv;
#pragma unroll
            for (int i = j + 1; i < 6; i++) {
                float sij = M[i * (i + 1) / 2 + j];
#pragma unroll
                for (int k2 = 0; k2 < j; k2++)
                    sij -= M[i * (i + 1) / 2 + k2] * M[j * (j + 1) / 2 + k2];
                M[i * (i + 1) / 2 + j] = sij * iv;
            }
        }

        // L y = rhs ; L^T x = y
        float xv[6];
        {
            float yv[6];
#pragma unroll
            for (int i = 0; i < 6; i++) {
                float s2 = r6[i];
#pragma unroll
                for (int k2 = 0; k2 < i; k2++) s2 -= M[i * (i + 1) / 2 + k2] * yv[k2];
                yv[i] = s2 * invd[i];
            }
#pragma unroll
            for (int i = 5; i >= 0; i--) {
                float s2 = yv[i];
#pragma unroll
                for (int k2 = i + 1; k2 < 6; k2++) s2 -= M[k2 * (k2 + 1) / 2 + i] * xv[k2];
                xv[i] = s2 * invd[i];
            }
        }

        float2* op = reinterpret_cast<float2*>(out + (size_t)p * 6);
        op[0] = make_float2(xv[0], xv[1]);
        op[1] = make_float2(xv[2], xv[3]);
        op[2] = make_float2(xv[4], xv[5]);
    }
}

extern "C" void kernel_launch(void* const* d_in, const int* in_sizes, int n_in,
                              void* d_out, int out_size)
{
    const float* feat0 = (const float*)d_in[0];
    const float* feat1 = (const float*)d_in[1];
    const float* flow  = (const float*)d_in[2];
    float* out = (float*)d_out;
    quadfit_kernel<<<(YD * XD) / 256, 256>>>(feat0, feat1, flow, out);
}

// round 9
// speedup vs baseline: 1.4661x; 1.0185x over previous
#include <cuda_runtime.h>

#define YD 384
#define XD 512
#define EPSR 1e-4f

typedef unsigned long long u64;

__device__ __forceinline__ u64 f2sub(u64 a, u64 b) {
    u64 r; asm("sub.rn.f32x2 %0,%1,%2;" : "=l"(r) : "l"(a), "l"(b)); return r;
}
__device__ __forceinline__ u64 f2mul(u64 a, u64 b) {
    u64 r; asm("mul.rn.f32x2 %0,%1,%2;" : "=l"(r) : "l"(a), "l"(b)); return r;
}
__device__ __forceinline__ u64 f2fma(u64 a, u64 b, u64 c) {
    u64 r; asm("fma.rn.f32x2 %0,%1,%2,%3;" : "=l"(r) : "l"(a), "l"(b), "l"(c)); return r;
}
__device__ __forceinline__ u64 pack2(float lo, float hi) {
    u64 r; asm("mov.b64 %0,{%1,%2};" : "=l"(r) : "f"(lo), "f"(hi)); return r;
}

// lerp on a 16-byte pair-of-pairs: v = a + w*(b-a), elementwise (FSUB+FFMA, matches scalar)
__device__ __forceinline__ ulonglong2 lerp2(ulonglong2 a, ulonglong2 b, u64 w2) {
    ulonglong2 r;
    r.x = f2fma(w2, f2sub(b.x, a.x), a.x);
    r.y = f2fma(w2, f2sub(b.y, a.y), a.y);
    return r;
}
// SSD over the 4 packed channels
__device__ __forceinline__ float cost2(ulonglong2 f0, ulonglong2 v) {
    u64 d0 = f2sub(f0.x, v.x);
    u64 d1 = f2sub(f0.y, v.y);
    u64 acc = f2fma(d1, d1, f2mul(d0, d0));
    float lo, hi; asm("mov.b64 {%0,%1},%2;" : "=f"(lo), "=f"(hi) : "l"(acc));
    return lo + hi;
}

__global__ __launch_bounds__(256) void quadfit_kernel(
    const float* __restrict__ feat0,
    const float* __restrict__ feat1,
    const float* __restrict__ flow,
    float* __restrict__ out)
{
    __shared__ float c_s[256 * 9];
    const int w    = threadIdx.x >> 5;   // warp 0..7
    const int lane = threadIdx.x & 31;
    const int g    = lane >> 3;          // pixel group within warp 0..3
    const int s    = lane & 7;           // sublane = 16-byte channel slot 0..7
    const int base = blockIdx.x * 256;

    const ulonglong2* __restrict__ f0q = (const ulonglong2*)feat0;
    const ulonglong2* __restrict__ f1q = (const ulonglong2*)feat1;
    const float4*     __restrict__ f1v = (const float4*)feat1;

    // ---------------- Phase A: 4 pixels per warp, 8 lanes (16B) per pixel ----------------
#pragma unroll 1
    for (int it = 0; it < 8; ++it) {
        const int li  = it * 32 + w * 4 + g;  // local pixel in block
        const int p   = base + li;            // linear pixel
        const int pyi = p >> 9;               // X = 512
        const int pxi = p & 511;

        const float u = __ldg(flow + p * 3 + 0);
        const float v = __ldg(flow + p * 3 + 1);
        const float px = (float)pxi + u;
        const float py = (float)pyi + v;
        const float bxf = floorf(px), byf = floorf(py);
        const float wx = px - bxf, wy = py - byf;
        const int bx = (int)bxf, by = (int)byf;

        float c[9];
        const bool interior = (bx >= 1) && (bx <= XD - 3) && (by >= 1) && (by <= YD - 3);
        if (interior) {
            const u64 wx2 = pack2(wx, wx);
            const u64 wy2 = pack2(wy, wy);
            const ulonglong2 f0 = f0q[p * 8 + s];

            const ulonglong2* rp = f1q + ((size_t)(by - 1) * XD + (bx - 1)) * 8 + s;
            ulonglong2 hp0, hp1, hp2;   // previous row horizontal lerps
            {
                ulonglong2 p0 = rp[0];
                ulonglong2 p1 = rp[8];
                ulonglong2 p2 = rp[16];
                ulonglong2 p3 = rp[24];
                hp0 = lerp2(p0, p1, wx2);
                hp1 = lerp2(p1, p2, wx2);
                hp2 = lerp2(p2, p3, wx2);
            }
#pragma unroll
            for (int r = 1; r < 4; r++) {
                const ulonglong2* q = rp + r * (XD * 8);
                ulonglong2 p0 = q[0];
                ulonglong2 p1 = q[8];
                ulonglong2 p2 = q[16];
                ulonglong2 p3 = q[24];
                ulonglong2 hc0 = lerp2(p0, p1, wx2);
                ulonglong2 hc1 = lerp2(p1, p2, wx2);
                ulonglong2 hc2 = lerp2(p2, p3, wx2);
                c[(r - 1) * 3 + 0] = cost2(f0, lerp2(hp0, hc0, wy2));
                c[(r - 1) * 3 + 1] = cost2(f0, lerp2(hp1, hc1, wy2));
                c[(r - 1) * 3 + 2] = cost2(f0, lerp2(hp2, hc2, wy2));
                hp0 = hc0; hp1 = hc1; hp2 = hc2;
            }
        } else {
            // exact clamped path (matches reference: x1 = clip(clip(x0)+1))
            const float4 f0 = ((const float4*)feat0)[p * 8 + s];
#pragma unroll 1
            for (int k = 0; k < 9; k++) {
                const int ox = k % 3 - 1, oy = k / 3 - 1;
                int x0 = min(max(bx + ox, 0), XD - 1);
                int x1 = min(x0 + 1, XD - 1);
                int y0 = min(max(by + oy, 0), YD - 1);
                int y1 = min(y0 + 1, YD - 1);
                float4 f00 = __ldg(f1v + ((size_t)y0 * XD + x0) * 8 + s);
                float4 f01 = __ldg(f1v + ((size_t)y0 * XD + x1) * 8 + s);
                float4 f10 = __ldg(f1v + ((size_t)y1 * XD + x0) * 8 + s);
                float4 f11 = __ldg(f1v + ((size_t)y1 * XD + x1) * 8 + s);
                float tx = f00.x + wx * (f01.x - f00.x);
                float ty = f00.y + wx * (f01.y - f00.y);
                float tz = f00.z + wx * (f01.z - f00.z);
                float tw = f00.w + wx * (f01.w - f00.w);
                float bxv = f10.x + wx * (f11.x - f10.x);
                float byv = f10.y + wx * (f11.y - f10.y);
                float bzv = f10.z + wx * (f11.z - f10.z);
                float bwv = f10.w + wx * (f11.w - f10.w);
                float vx = tx + wy * (bxv - tx);
                float vy = ty + wy * (byv - ty);
                float vz = tz + wy * (bzv - tz);
                float vw = tw + wy * (bwv - tw);
                float dx = f0.x - vx, dy = f0.y - vy, dz = f0.z - vz, dw = f0.w - vw;
                c[k] = dx * dx + dy * dy + dz * dz + dw * dw;
            }
        }

        // batch butterfly reduce (9 independent 3-deep chains — full ILP)
#pragma unroll
        for (int k = 0; k < 9; k++) {
            float vr = c[k];
            vr += __shfl_xor_sync(0xffffffffu, vr, 4);
            vr += __shfl_xor_sync(0xffffffffu, vr, 2);
            vr += __shfl_xor_sync(0xffffffffu, vr, 1);
            c[k] = vr;
        }
        if (s == 0) {
#pragma unroll
            for (int k = 0; k < 9; k++) c_s[li * 9 + k] = c[k];
        }
    }

    __syncthreads();

    // ---------------- Phase B: thread-per-pixel softmax + 6x6 solve (R2 verbatim) ----------------
    {
        const int t = threadIdx.x;
        const int p = base + t;

        float c[9];
#pragma unroll
        for (int k = 0; k < 9; k++) c[k] = c_s[t * 9 + k];

        // softmax(-c): weights
        float m = c[0];
#pragma unroll
        for (int k = 1; k < 9; k++) m = fminf(m, c[k]);
        float wgt[9];
        float sums = 0.f;
#pragma unroll
        for (int k = 0; k < 9; k++) { wgt[k] = __expf(m - c[k]); sums += wgt[k]; }
        const float inv_s = 1.f / sums;
#pragma unroll
        for (int k = 0; k < 9; k++) wgt[k] *= inv_s;

        // AtWA (lower triangle, idx(i,j)=i*(i+1)/2+j) and rhs
        float M[21];
        float r6[6];
#pragma unroll
        for (int i = 0; i < 21; i++) M[i] = 0.f;
#pragma unroll
        for (int i = 0; i < 6; i++) r6[i] = 0.f;
#pragma unroll
        for (int k = 0; k < 9; k++) {
            const float ox = (float)(k % 3 - 1);
            const float oy = (float)(k / 3 - 1);
            const float a[6] = {ox * ox, oy * oy, ox * oy, ox, oy, 1.f};
            const float wk = wgt[k];
            const float wc = wk * c[k];
            int idx = 0;
#pragma unroll
            for (int i = 0; i < 6; i++) {
                r6[i] += a[i] * wc;
#pragma unroll
                for (int j = 0; j <= i; j++) { M[idx] += a[i] * a[j] * wk; idx++; }
            }
        }
        M[0] += EPSR; M[2] += EPSR; M[5] += EPSR; M[9] += EPSR; M[14] += EPSR; M[20] += EPSR;

        // Cholesky factorization
        float Lm[21];
        float invd[6];
#pragma unroll
        for (int j = 0; j < 6; j++) {
            float d = M[j * (j + 1) / 2 + j];
#pragma unroll
            for (int k2 = 0; k2 < j; k2++) { float l = Lm[j * (j + 1) / 2 + k2]; d -= l * l; }
            const float iv = rsqrtf(d);
            invd[j] = iv;
            Lm[j * (j + 1) / 2 + j] = d * iv;
#pragma unroll
            for (int i = j + 1; i < 6; i++) {
                float sij = M[i * (i + 1) / 2 + j];
#pragma unroll
                for (int k2 = 0; k2 < j; k2++)
                    sij -= Lm[i * (i + 1) / 2 + k2] * Lm[j * (j + 1) / 2 + k2];
                Lm[i * (i + 1) / 2 + j] = sij * iv;
            }
        }

        // triangular solves: L y = b ; L^T x = y
        float xv[6];
        {
            float yv[6];
#pragma unroll
            for (int i = 0; i < 6; i++) {
                float s2 = r6[i];
#pragma unroll
                for (int k2 = 0; k2 < i; k2++) s2 -= Lm[i * (i + 1) / 2 + k2] * yv[k2];
                yv[i] = s2 * invd[i];
            }
#pragma unroll
            for (int i = 5; i >= 0; i--) {
                float s2 = yv[i];
#pragma unroll
                for (int k2 = i + 1; k2 < 6; k2++) s2 -= Lm[k2 * (k2 + 1) / 2 + i] * xv[k2];
                xv[i] = s2 * invd[i];
            }
        }

        // one iterative-refinement step: x += solve(M, rhs - M x)
        {
            float resid[6];
#pragma unroll
            for (int i = 0; i < 6; i++) {
                float acc = r6[i];
#pragma unroll
                for (int j = 0; j < 6; j++) {
                    const int hi = (i > j) ? i : j;
                    const int lo = (i > j) ? j : i;
                    acc -= M[hi * (hi + 1) / 2 + lo] * xv[j];
                }
                resid[i] = acc;
            }
            float yv[6];
#pragma unroll
            for (int i = 0; i < 6; i++) {
                float s2 = resid[i];
#pragma unroll
                for (int k2 = 0; k2 < i; k2++) s2 -= Lm[i * (i + 1) / 2 + k2] * yv[k2];
                yv[i] = s2 * invd[i];
            }
            float dx[6];
#pragma unroll
            for (int i = 5; i >= 0; i--) {
                float s2 = yv[i];
#pragma unroll
                for (int k2 = i + 1; k2 < 6; k2++) s2 -= Lm[k2 * (k2 + 1) / 2 + i] * dx[k2];
                dx[i] = s2 * invd[i];
            }
#pragma unroll
            for (int i = 0; i < 6; i++) xv[i] += dx[i];
        }

        float2* op = reinterpret_cast<float2*>(out + (size_t)p * 6);
        op[0] = make_float2(xv[0], xv[1]);
        op[1] = make_float2(xv[2], xv[3]);
        op[2] = make_float2(xv[4], xv[5]);
    }
}

extern "C" void kernel_launch(void* const* d_in, const int* in_sizes, int n_in,
                              void* d_out, int out_size)
{
    const float* feat0 = (const float*)d_in[0];
    const float* feat1 = (const float*)d_in[1];
    const float* flow  = (const float*)d_in[2];
    float* out = (float*)d_out;
    quadfit_kernel<<<(YD * XD) / 256, 256>>>(feat0, feat1, flow, out);
}